// round 15
// baseline (speedup 1.0000x reference)
#include <cuda_runtime.h>
#include <cuda_fp16.h>
#include <math.h>
#include <stdint.h>

#define Bb 4
#define LQ 640
#define LIMt 1296
#define LKt 1936
#define DM 768
#define NH 12
#define DKh 64
#define DFFn 3072
#define MD 100
#define KVS 1536
#define MQn (Bb*LQ)    // 2560
#define MKn (Bb*LKt)   // 7744
#define BHn (Bb*NH)    // 48

// ================= helpers =================
__device__ __forceinline__ uint32_t smem_to_u32(const void* p) {
    uint32_t a;
    asm("{ .reg .u64 t; cvta.to.shared.u64 t, %1; cvt.u32.u64 %0, t; }" : "=r"(a) : "l"(p));
    return a;
}
__device__ __forceinline__ void cp_async16(uint32_t dst, const void* src, int src_bytes) {
    asm volatile("cp.async.cg.shared.global [%0], [%1], 16, %2;"
                 :: "r"(dst), "l"(src), "r"(src_bytes) : "memory");
}
__device__ __forceinline__ void cp_async4(uint32_t dst, const void* src, int src_bytes) {
    asm volatile("cp.async.ca.shared.global [%0], [%1], 4, %2;"
                 :: "r"(dst), "l"(src), "r"(src_bytes) : "memory");
}
__device__ __forceinline__ void cp_commit() {
    asm volatile("cp.async.commit_group;" ::: "memory");
}
template<int N>
__device__ __forceinline__ void cp_wait() {
    asm volatile("cp.async.wait_group %0;" :: "n"(N) : "memory");
}
__device__ __forceinline__ void ldm_x4(uint32_t& r0, uint32_t& r1, uint32_t& r2, uint32_t& r3,
                                       uint32_t addr) {
    asm volatile("ldmatrix.sync.aligned.m8n8.x4.shared.b16 {%0,%1,%2,%3}, [%4];"
                 : "=r"(r0), "=r"(r1), "=r"(r2), "=r"(r3) : "r"(addr));
}
__device__ __forceinline__ void ldm_x4t(uint32_t& r0, uint32_t& r1, uint32_t& r2, uint32_t& r3,
                                        uint32_t addr) {
    asm volatile("ldmatrix.sync.aligned.m8n8.x4.trans.shared.b16 {%0,%1,%2,%3}, [%4];"
                 : "=r"(r0), "=r"(r1), "=r"(r2), "=r"(r3) : "r"(addr));
}
__device__ __forceinline__ void mma16816(float& d0, float& d1, float& d2, float& d3,
                                         uint32_t a0, uint32_t a1, uint32_t a2, uint32_t a3,
                                         uint32_t b0, uint32_t b1) {
    asm volatile("mma.sync.aligned.m16n8k16.row.col.f32.f16.f16.f32 "
                 "{%0,%1,%2,%3}, {%4,%5,%6,%7}, {%8,%9}, {%0,%1,%2,%3};"
                 : "+f"(d0), "+f"(d1), "+f"(d2), "+f"(d3)
                 : "r"(a0), "r"(a1), "r"(a2), "r"(a3), "r"(b0), "r"(b1));
}

// ================= scratch =================
__device__ float g_tmp [Bb*LQ*DM];
__device__ float g_tmp2[Bb*LQ*DM];
__device__ float g_src1[Bb*LQ*DM];
__device__ float g_bkv [KVS];
__device__ float g_zeros[DFFn];
__device__ float g_po[2*BHn*LQ*DKh];
__device__ float g_pl[2*BHn*LQ];

__device__ __half g_full[Bb*LKt*DM];
__device__ __half g_q   [Bb*LQ*DM];
__device__ __half g_kv  [Bb*LKt*KVS];
__device__ __half g_ctx [Bb*LQ*DM];
__device__ __half g_s1  [Bb*LQ*DM];
__device__ __half g_f1  [Bb*LQ*DFFn];
__device__ __half g_wq16[DM*DM];
__device__ __half g_wk16[DM*DM];
__device__ __half g_wv16[DM*DM];
__device__ __half g_wo16[DM*DM];
__device__ __half g_w116[DM*DFFn];
__device__ __half g_w216[DFFn*DM];

// ================= converts =================
__global__ void concat_f16_kernel(const float* __restrict__ im, const float* __restrict__ doc,
                                  __half* __restrict__ O) {
    int i = blockIdx.x * blockDim.x + threadIdx.x;
    const int total4 = Bb*LKt*(DM/4);
    if (i >= total4) return;
    int d4 = i % (DM/4); int bt = i / (DM/4);
    int b = bt / LKt, t = bt % LKt;
    const float* src = (t < LIMt) ? im + ((size_t)b*LIMt + t)*DM
                                  : doc + ((size_t)b*LQ + (t - LIMt))*DM;
    float4 v = *(const float4*)(src + d4*4);
    __half2* o = (__half2*)(O + (size_t)i*4);
    o[0] = __floats2half2_rn(v.x, v.y);
    o[1] = __floats2half2_rn(v.z, v.w);
}

#define SWF4   147456
#define W1F4   589824
#define SEG_W1 (4*SWF4)
#define SEG_W2 (SEG_W1 + W1F4)
#define SEG_WEND (SEG_W2 + W1F4)

__global__ void wconv_w_kernel(
    const float* __restrict__ Wq, const float* __restrict__ Wk,
    const float* __restrict__ Wv, const float* __restrict__ Wo,
    const float* __restrict__ W1, const float* __restrict__ W2,
    __half* __restrict__ q16, __half* __restrict__ k16,
    __half* __restrict__ v16, __half* __restrict__ o16,
    __half* __restrict__ w116, __half* __restrict__ w216)
{
    int i = blockIdx.x * blockDim.x + threadIdx.x;
    if (i >= SEG_WEND) return;
    const float* src; __half* dst; int j;
    if (i < SEG_W1) {
        int seg = i / SWF4; j = i - seg*SWF4;
        src = seg==0 ? Wq : seg==1 ? Wk : seg==2 ? Wv : Wo;
        dst = seg==0 ? q16 : seg==1 ? k16 : seg==2 ? v16 : o16;
    } else if (i < SEG_W2) { j = i - SEG_W1; src = W1; dst = w116; }
    else                   { j = i - SEG_W2; src = W2; dst = w216; }
    float4 v = ((const float4*)src)[j];
    __half2* o = (__half2*)(dst + (size_t)j*4);
    o[0] = __floats2half2_rn(v.x, v.y);
    o[1] = __floats2half2_rn(v.z, v.w);
}

__global__ void bias_cat_kernel(const float* __restrict__ bk, const float* __restrict__ bv,
                                float* __restrict__ bkv) {
    int i = blockIdx.x * blockDim.x + threadIdx.x;
    if (i < DM) bkv[i] = bk[i];
    else if (i < KVS) bkv[i] = bv[i - DM];
}

// ================= fp16 HMMA GEMM body =================
#define KT 64
#define AROWB 144
#define ATILEB (128*AROWB)
#define BROWB 272
#define BTILEB (64*BROWB)
#define STAGEB (ATILEB+BTILEB)
#define GEMM_SMEM (3*STAGEB)  // 107520

template<int OUTM, bool RELU>
__device__ __forceinline__ void gemm_body(
    const __half* __restrict__ A, int lda, int arow0, bool guard, int M, int m0,
    const __half* __restrict__ Bp, int ldb, int nc0,
    const float* __restrict__ bias, int n0,
    float* __restrict__ C, __half* __restrict__ O16, int ldo,
    int K, uint32_t sbase)
{
    const int tid = threadIdx.x, wid = tid >> 5, lane = tid & 31;
    const int wm = wid & 1, wn = wid >> 1;
    const int KC = K / KT;

    float acc[4][4][4];
    #pragma unroll
    for (int i=0;i<4;i++)
        #pragma unroll
        for (int j=0;j<4;j++)
            #pragma unroll
            for (int r=0;r<4;r++) acc[i][j][r] = 0.f;

    const int lr = tid >> 3;
    const int lc = tid & 7;

    auto issue_chunk = [&](int c) {
        const int buf = c % 3;
        const int k0 = c * KT;
        uint32_t sA = sbase + buf * STAGEB;
        uint32_t sB = sA + ATILEB;
        #pragma unroll
        for (int it = 0; it < 4; it++) {
            int r = lr + it * 32;
            int nb = (!guard || (m0 + r) < M) ? 16 : 0;
            cp_async16(sA + r*AROWB + lc*16,
                       A + (size_t)(arow0 + r) * lda + k0 + lc*8, nb);
        }
        #pragma unroll
        for (int it = 0; it < 4; it++) {
            int e = tid + it * 256;
            int rb = e >> 4, cb = e & 15;
            cp_async16(sB + rb*BROWB + cb*16,
                       Bp + (size_t)(k0 + rb) * ldb + nc0 + cb*8, 16);
        }
        cp_commit();
    };

    issue_chunk(0);
    issue_chunk(1);
    for (int c = 0; c < KC; c++) {
        if (c + 2 < KC)      { issue_chunk(c + 2); cp_wait<2>(); }
        else if (c + 1 < KC) { cp_wait<1>(); }
        else                 { cp_wait<0>(); }
        __syncthreads();

        const int buf = c % 3;
        uint32_t sA = sbase + buf * STAGEB;
        uint32_t sB = sA + ATILEB;
        uint32_t aRowBase = sA + (wm*64 + (lane & 15)) * AROWB + (lane >> 4) * 16;
        uint32_t bTBase   = sB + (((lane >> 3) & 1)*8 + (lane & 7)) * BROWB
                               + (lane >> 4) * 16 + wn*64;

        #pragma unroll
        for (int ks = 0; ks < 4; ks++) {
            uint32_t bfr[4][2];
            #pragma unroll
            for (int g = 0; g < 2; g++) {
                uint32_t r0, r1, r2, r3;
                ldm_x4t(r0, r1, r2, r3, bTBase + ks*16*BROWB + g*32);
                bfr[g*2+0][0] = r0; bfr[g*2+0][1] = r1;
                bfr[g*2+1][0] = r2; bfr[g*2+1][1] = r3;
            }
            #pragma unroll
            for (int mt = 0; mt < 4; mt++) {
                uint32_t a0, a1, a2, a3;
                ldm_x4(a0, a1, a2, a3, aRowBase + mt*16*AROWB + ks*32);
                #pragma unroll
                for (int nt = 0; nt < 4; nt++)
                    mma16816(acc[mt][nt][0], acc[mt][nt][1], acc[mt][nt][2], acc[mt][nt][3],
                             a0, a1, a2, a3, bfr[nt][0], bfr[nt][1]);
            }
        }
        __syncthreads();
    }

    const int mr = lane >> 2, nc = (lane & 3) * 2;
    #pragma unroll
    for (int mt = 0; mt < 4; mt++) {
        #pragma unroll
        for (int half = 0; half < 2; half++) {
            int m = m0 + wm*64 + mt*16 + mr + half*8;
            if (guard && m >= M) continue;
            #pragma unroll
            for (int nt = 0; nt < 4; nt++) {
                int n = n0 + wn*32 + nt*8 + nc;
                float v0 = acc[mt][nt][half*2+0] + bias[n];
                float v1 = acc[mt][nt][half*2+1] + bias[n+1];
                if (RELU) { v0 = fmaxf(v0, 0.f); v1 = fmaxf(v1, 0.f); }
                size_t o = (size_t)m * ldo + n;
                if (OUTM == 1) {
                    *reinterpret_cast<__half2*>(O16 + o) = __floats2half2_rn(v0, v1);
                } else {
                    C[o] = v0; C[o+1] = v1;
                }
            }
        }
    }
}

template<int OUTM, bool RELU>
__global__ void __launch_bounds__(256,2) gemm_f16_kernel(
    const __half* __restrict__ A, const __half* __restrict__ Bp, int ldb,
    const float* __restrict__ bias,
    float* __restrict__ C, __half* __restrict__ O16,
    int M, int N, int K)
{
    extern __shared__ char smem[];
    int m0 = blockIdx.y * 128, n0 = blockIdx.x * 128;
    gemm_body<OUTM,RELU>(A, K, m0, true, M, m0, Bp, ldb, n0, bias, n0,
                         C, O16, N, K, smem_to_u32(smem));
}

__global__ void __launch_bounds__(256,2) gemm_f16_splitk_kernel(
    const __half* __restrict__ A, int lda,
    const __half* __restrict__ Bp, int ldb,
    const float* __restrict__ bias, const float* __restrict__ zbias,
    float* __restrict__ C0, float* __restrict__ C1,
    int M, int N, int Ksl)
{
    extern __shared__ char smem[];
    int m0 = blockIdx.y * 128, n0 = blockIdx.x * 128;
    int z = blockIdx.z;
    int kofs = z * Ksl;
    gemm_body<0,false>(A + kofs, lda, m0, true, M, m0,
                       Bp + (size_t)kofs*ldb, ldb, n0,
                       z ? zbias : bias, n0,
                       z ? C1 : C0, nullptr, N, Ksl, smem_to_u32(smem));
}

__global__ void __launch_bounds__(256,2) qkv_kernel(
    const __half* __restrict__ full,
    const __half* __restrict__ wq, const __half* __restrict__ wk, const __half* __restrict__ wv,
    const float* __restrict__ bq, const float* __restrict__ bkv,
    __half* __restrict__ q, __half* __restrict__ kv)
{
    extern __shared__ char smem[];
    uint32_t sbase = smem_to_u32(smem);
    int id = blockIdx.x;
    if (id < 732) {
        int bx = id % 12, by = id / 12;
        int m0 = by*128, n0 = bx*128;
        const __half* Bp = (n0 < DM) ? wk : wv;
        int nc0 = (n0 < DM) ? n0 : n0 - DM;
        gemm_body<1,false>(full, DM, m0, true, MKn, m0, Bp, DM, nc0, bkv, n0,
                           nullptr, kv, KVS, DM, sbase);
    } else {
        int id2 = id - 732;
        int bx = id2 % 6, by = id2 / 6;
        int m0 = by*128, n0 = bx*128;
        int arow0 = (by/5)*LKt + LIMt + (by%5)*128;
        gemm_body<1,false>(full, DM, arow0, false, MQn, m0, wq, DM, n0, bq, n0,
                           nullptr, q, DM, DM, sbase);
    }
}

// ================= fp16 HMMA flash attention, split-K2, fixed-max, MUFU exp =================
#define ATS 72
#define ATSB 144

struct AttnSmem3 {
    __half Q[64*ATS];
    __half K[2][64*ATS], V[2][64*ATS];
    float bx[201], by[201];
    int qx[64], qy[64];
    int2 kxy[2][64];
};

#define CSC 0.18033688011116f   /* 0.125 * log2(e) */
#define M0H 3.0f

__global__ void __launch_bounds__(128,4) attn_kernel(
    const __half* __restrict__ qg, const __half* __restrict__ kvg,
    const int* __restrict__ dqx, const int* __restrict__ dqy,
    const int* __restrict__ imx, const int* __restrict__ imy,
    const float* __restrict__ bias_x, const float* __restrict__ bias_y,
    float* __restrict__ po, float* __restrict__ pl)
{
    extern __shared__ char smem_raw[];
    AttnSmem3& S = *reinterpret_cast<AttnSmem3*>(smem_raw);
    const int tid = threadIdx.x;
    const int lane = tid & 31, w = tid >> 5;
    const int qt = blockIdx.x;
    const int bh = blockIdx.y;
    const int z  = blockIdx.z;
    const int b = bh / NH, h = bh % NH;
    const int qbase = qt * 64;
    const int bLK = b * LKt;
    const int hd = h * DKh;

    const int NT = (LKt + 63) / 64;      // 31
    const int kt0 = z * 16;
    const int kt1 = z ? NT : 16;

    const uint32_t sQ = smem_to_u32(S.Q);
    uint32_t sK[2] = { smem_to_u32(S.K[0]), smem_to_u32(S.K[1]) };
    uint32_t sV[2] = { smem_to_u32(S.V[0]), smem_to_u32(S.V[1]) };
    uint32_t sKxy[2] = { smem_to_u32(S.kxy[0]), smem_to_u32(S.kxy[1]) };

    #pragma unroll
    for (int it = 0; it < 4; it++) {
        int ch = tid + it*128;
        int row = ch >> 3, off = (ch & 7) * 8;
        size_t g = (size_t)(b*LQ + qbase + row)*DM + hd + off;
        *(float4*)((char*)S.Q + row*ATSB + off*2) = *(const float4*)(qg + g);
    }
    const float LOG2E = 1.4426950408889634f;
    for (int i = tid; i < 201; i += 128) {
        S.bx[i] = fmaf(bias_x[i*NH + h], LOG2E, -M0H);
        S.by[i] = fmaf(bias_y[i*NH + h], LOG2E, -M0H);
    }
    if (tid < 64) S.qx[tid] = dqx[b*LQ + qbase + tid];
    else if (tid < 128) S.qy[tid-64] = dqy[b*LQ + qbase + (tid-64)];

    auto issue_kv = [&](int kt) {
        const int buf = kt & 1;
        const int kbase = kt * 64;
        #pragma unroll
        for (int it = 0; it < 4; it++) {
            int ch = tid + it*128;
            int row = ch >> 3, off = (ch & 7) * 8;
            int kg = kbase + row;
            int nb = kg < LKt ? 16 : 0;
            size_t g = (size_t)(bLK + kg)*KVS + hd + off;
            uint32_t so = row*ATSB + off*2;
            cp_async16(sK[buf] + so, kvg + g, nb);
            cp_async16(sV[buf] + so, kvg + g + DM, nb);
        }
        {
            int j = tid & 63;
            int kg = kbase + j;
            const int* src;
            if (tid < 64) src = (kg < LIMt) ? (imx + b*LIMt + kg) : (dqx + b*LQ + (kg - LIMt));
            else          src = (kg < LIMt) ? (imy + b*LIMt + kg) : (dqy + b*LQ + (kg - LIMt));
            uint32_t dst = sKxy[buf] + j*8 + (tid < 64 ? 0 : 4);
            cp_async4(dst, src, kg < LKt ? 4 : 0);
        }
        cp_commit();
    };

    issue_kv(kt0);
    __syncthreads();

    const int r1 = w*16 + (lane >> 2);
    const int qx1 = S.qx[r1],   qy1 = S.qy[r1];
    const int qx2 = S.qx[r1+8], qy2 = S.qy[r1+8];

    uint32_t qa[4][4];
    {
        uint32_t aBase = (w*16 + (lane & 15))*ATSB + (lane >> 4)*16;
        #pragma unroll
        for (int s = 0; s < 4; s++)
            ldm_x4(qa[s][0], qa[s][1], qa[s][2], qa[s][3], sQ + aBase + s*32);
    }

    float oacc[8][4];
    #pragma unroll
    for (int d=0; d<8; d++)
        #pragma unroll
        for (int r=0; r<4; r++) oacc[d][r] = 0.f;
    float l1 = 0.f, l2 = 0.f;

    for (int kt = kt0; kt < kt1; kt++) {
        if (kt > kt0) __syncthreads();
        if (kt + 1 < kt1) { issue_kv(kt + 1); cp_wait<1>(); }
        else              { cp_wait<0>(); }
        __syncthreads();

        const int buf = kt & 1;
        const int kbase = kt * 64;

        float sc[8][4];
        #pragma unroll
        for (int nt=0; nt<8; nt++)
            #pragma unroll
            for (int r=0; r<4; r++) sc[nt][r] = 0.f;

        uint32_t bBase = (lane & 15)*ATSB + (lane >> 4)*16;
        #pragma unroll
        for (int s = 0; s < 4; s++) {
            uint32_t bf[8][2];
            #pragma unroll
            for (int np = 0; np < 4; np++) {
                uint32_t r0, r1_, r2_, r3_;
                ldm_x4(r0, r1_, r2_, r3_, sK[buf] + bBase + np*16*ATSB + s*32);
                bf[np*2+0][0] = r0;  bf[np*2+0][1] = r2_;
                bf[np*2+1][0] = r1_; bf[np*2+1][1] = r3_;
            }
            #pragma unroll
            for (int nt = 0; nt < 8; nt++)
                mma16816(sc[nt][0], sc[nt][1], sc[nt][2], sc[nt][3],
                         qa[s][0], qa[s][1], qa[s][2], qa[s][3], bf[nt][0], bf[nt][1]);
        }

        // ---- bias + exp: uniform specialization (30/31 tiles skip masking) ----
        #define BIAS_EXP_BODY(FULL)                                                    \
        {                                                                              \
            _Pragma("unroll")                                                          \
            for (int nt = 0; nt < 8; nt++) {                                           \
                _Pragma("unroll")                                                      \
                for (int e = 0; e < 2; e++) {                                          \
                    int c = nt*8 + (lane & 3)*2 + e;                                   \
                    int2 kk = S.kxy[buf][c];                                           \
                    int rx1 = qx1 - kk.x; rx1 = rx1 < -MD ? -MD : (rx1 > MD ? MD : rx1); \
                    int ry1 = qy1 - kk.y; ry1 = ry1 < -MD ? -MD : (ry1 > MD ? MD : ry1); \
                    float b1v = S.bx[rx1 + MD] + S.by[ry1 + MD];                       \
                    float p0 = exp2f(fmaf(sc[nt][e], CSC, b1v));                       \
                    int rx2 = qx2 - kk.x; rx2 = rx2 < -MD ? -MD : (rx2 > MD ? MD : rx2); \
                    int ry2 = qy2 - kk.y; ry2 = ry2 < -MD ? -MD : (ry2 > MD ? MD : ry2); \
                    float b2v = S.bx[rx2 + MD] + S.by[ry2 + MD];                       \
                    float p1 = exp2f(fmaf(sc[nt][2+e], CSC, b2v));                     \
                    if (!FULL) {                                                       \
                        bool valid = (kbase + c) < LKt;                                \
                        p0 = valid ? p0 : 0.f;                                         \
                        p1 = valid ? p1 : 0.f;                                         \
                    }                                                                  \
                    sc[nt][e] = p0;   l1 += p0;                                        \
                    sc[nt][2+e] = p1; l2 += p1;                                        \
                }                                                                      \
            }                                                                          \
        }
        if (kbase + 64 <= LKt) BIAS_EXP_BODY(true)
        else                   BIAS_EXP_BODY(false)
        #undef BIAS_EXP_BODY

        // ---- O += P V (pack pa inside the loop) ----
        uint32_t vBase = (((lane >> 3) & 1)*8 + (lane & 7))*ATSB + (lane >> 4)*16;
        #pragma unroll
        for (int t = 0; t < 4; t++) {
            uint32_t pa0, pa1, pa2, pa3;
            {
                __half2 h0 = __floats2half2_rn(sc[2*t][0],   sc[2*t][1]);
                __half2 h1 = __floats2half2_rn(sc[2*t][2],   sc[2*t][3]);
                __half2 h2 = __floats2half2_rn(sc[2*t+1][0], sc[2*t+1][1]);
                __half2 h3 = __floats2half2_rn(sc[2*t+1][2], sc[2*t+1][3]);
                pa0 = *reinterpret_cast<uint32_t*>(&h0);
                pa1 = *reinterpret_cast<uint32_t*>(&h1);
                pa2 = *reinterpret_cast<uint32_t*>(&h2);
                pa3 = *reinterpret_cast<uint32_t*>(&h3);
            }
            #pragma unroll
            for (int dp = 0; dp < 4; dp++) {
                uint32_t v0, v1, v2, v3;
                ldm_x4t(v0, v1, v2, v3, sV[buf] + vBase + t*16*ATSB + dp*32);
                mma16816(oacc[dp*2][0], oacc[dp*2][1], oacc[dp*2][2], oacc[dp*2][3],
                         pa0, pa1, pa2, pa3, v0, v1);
                mma16816(oacc[dp*2+1][0], oacc[dp*2+1][1], oacc[dp*2+1][2], oacc[dp*2+1][3],
                         pa0, pa1, pa2, pa3, v2, v3);
            }
        }
    }

    // ---- partial row sums + partial O to scratch ----
    l1 += __shfl_xor_sync(0xffffffffu, l1, 1);
    l1 += __shfl_xor_sync(0xffffffffu, l1, 2);
    l2 += __shfl_xor_sync(0xffffffffu, l2, 1);
    l2 += __shfl_xor_sync(0xffffffffu, l2, 2);
    const int qrow1 = qbase + r1, qrow2 = qrow1 + 8;
    const size_t zofs = (size_t)z * BHn * LQ;
    if ((lane & 3) == 0) {
        pl[zofs + (size_t)bh*LQ + qrow1] = l1;
        pl[zofs + (size_t)bh*LQ + qrow2] = l2;
    }
    const size_t pbase1 = (zofs + (size_t)bh*LQ + qrow1) * DKh;
    const size_t pbase2 = (zofs + (size_t)bh*LQ + qrow2) * DKh;
    #pragma unroll
    for (int d = 0; d < 8; d++) {
        int colp = d*8 + (lane & 3)*2;
        *(float2*)(po + pbase1 + colp) = make_float2(oacc[d][0], oacc[d][1]);
        *(float2*)(po + pbase2 + colp) = make_float2(oacc[d][2], oacc[d][3]);
    }
}

// combine: ctx = (O0+O1)/(l0+l1), fp16
__global__ void __launch_bounds__(256) attn_combine_kernel(
    const float* __restrict__ po, const float* __restrict__ pl,
    __half* __restrict__ ctx)
{
    int t = blockIdx.x * blockDim.x + threadIdx.x;
    const int total = BHn*LQ*(DKh/2);
    if (t >= total) return;
    int d2 = (t & 31) * 2;
    int bhq = t >> 5;
    const size_t Z = (size_t)BHn*LQ;
    float l = pl[bhq] + pl[Z + bhq];
    float inv = 1.f / l;
    float2 o0 = *(const float2*)(po + (size_t)bhq*DKh + d2);
    float2 o1 = *(const float2*)(po + (Z + bhq)*DKh + d2);
    int bh = bhq / LQ, qr = bhq % LQ;
    int b = bh / NH, h = bh % NH;
    size_t o = ((size_t)(b*LQ + qr))*DM + h*DKh + d2;
    *reinterpret_cast<__half2*>(ctx + o) =
        __floats2half2_rn((o0.x + o1.x)*inv, (o0.y + o1.y)*inv);
}

// ================= fused add + LayerNorm =================
template<bool F16OUT, bool TWO>
__global__ void __launch_bounds__(256) addln_kernel(
    const float* __restrict__ A, const float* __restrict__ Cv, const float* __restrict__ Cv2,
    const float* __restrict__ g, const float* __restrict__ be,
    float* __restrict__ out, __half* __restrict__ O16)
{
    __shared__ float sred[256];
    const int row = blockIdx.x;
    const int tid = threadIdx.x;
    const size_t base = (size_t)row * DM;

    float x[3];
    #pragma unroll
    for (int i=0;i<3;i++) {
        int col = tid + 256*i;
        x[i] = A[base + col] + Cv[base + col];
        if (TWO) x[i] += Cv2[base + col];
    }
    float s = x[0] + x[1] + x[2];
    sred[tid] = s; __syncthreads();
    for (int off=128; off>0; off>>=1) {
        if (tid < off) sred[tid] += sred[tid+off];
        __syncthreads();
    }
    float mu = sred[0] * (1.f/DM);
    __syncthreads();
    float d0=x[0]-mu, d1=x[1]-mu, d2=x[2]-mu;
    sred[tid] = d0*d0 + d1*d1 + d2*d2; __syncthreads();
    for (int off=128; off>0; off>>=1) {
        if (tid < off) sred[tid] += sred[tid+off];
        __syncthreads();
    }
    float rs = rsqrtf(sred[0] * (1.f/DM) + 1e-5f);
    #pragma unroll
    for (int i=0;i<3;i++) {
        int col = tid + 256*i;
        float v = (x[i] - mu) * rs * g[col] + be[col];
        out[base + col] = v;
        if (F16OUT) O16[base + col] = __float2half_rn(v);
    }
}

// ================= launch =================
extern "C" void kernel_launch(void* const* d_in, const int* in_sizes, int n_in,
                              void* d_out, int out_size) {
    const float* docqa  = (const float*)d_in[0];
    const float* im     = (const float*)d_in[1];
    const int*   dqx    = (const int*)  d_in[2];
    const int*   dqy    = (const int*)  d_in[3];
    const int*   imx    = (const int*)  d_in[4];
    const int*   imy    = (const int*)  d_in[5];
    const float* Wq     = (const float*)d_in[6];
    const float* bq     = (const float*)d_in[7];
    const float* Wk     = (const float*)d_in[8];
    const float* bk     = (const float*)d_in[9];
    const float* Wv     = (const float*)d_in[10];
    const float* bv     = (const float*)d_in[11];
    const float* Wo     = (const float*)d_in[12];
    const float* bo     = (const float*)d_in[13];
    const float* bias_x = (const float*)d_in[14];
    const float* bias_y = (const float*)d_in[15];
    const float* W1     = (const float*)d_in[16];
    const float* b1     = (const float*)d_in[17];
    const float* W2     = (const float*)d_in[18];
    const float* b2     = (const float*)d_in[19];
    const float* g1     = (const float*)d_in[20];
    const float* be1    = (const float*)d_in[21];
    const float* g2     = (const float*)d_in[22];
    const float* be2    = (const float*)d_in[23];
    float* out = (float*)d_out;

    float *p_tmp, *p_tmp2, *p_src1, *p_bkv, *p_zeros, *p_po, *p_pl;
    cudaGetSymbolAddress((void**)&p_tmp,  g_tmp);
    cudaGetSymbolAddress((void**)&p_tmp2, g_tmp2);
    cudaGetSymbolAddress((void**)&p_src1, g_src1);
    cudaGetSymbolAddress((void**)&p_bkv,  g_bkv);
    cudaGetSymbolAddress((void**)&p_zeros,g_zeros);
    cudaGetSymbolAddress((void**)&p_po,   g_po);
    cudaGetSymbolAddress((void**)&p_pl,   g_pl);

    __half *full, *q, *kv, *ctx, *s1, *f1;
    __half *wq16, *wk16, *wv16, *wo16, *w116, *w216;
    cudaGetSymbolAddress((void**)&full, g_full);
    cudaGetSymbolAddress((void**)&q,    g_q);
    cudaGetSymbolAddress((void**)&kv,   g_kv);
    cudaGetSymbolAddress((void**)&ctx,  g_ctx);
    cudaGetSymbolAddress((void**)&s1,   g_s1);
    cudaGetSymbolAddress((void**)&f1,   g_f1);
    cudaGetSymbolAddress((void**)&wq16, g_wq16);
    cudaGetSymbolAddress((void**)&wk16, g_wk16);
    cudaGetSymbolAddress((void**)&wv16, g_wv16);
    cudaGetSymbolAddress((void**)&wo16, g_wo16);
    cudaGetSymbolAddress((void**)&w116, g_w116);
    cudaGetSymbolAddress((void**)&w216, g_w216);

    cudaFuncSetAttribute(qkv_kernel, cudaFuncAttributeMaxDynamicSharedMemorySize, GEMM_SMEM);
    cudaFuncSetAttribute(gemm_f16_kernel<0,false>, cudaFuncAttributeMaxDynamicSharedMemorySize, GEMM_SMEM);
    cudaFuncSetAttribute(gemm_f16_kernel<1,true >, cudaFuncAttributeMaxDynamicSharedMemorySize, GEMM_SMEM);
    cudaFuncSetAttribute(gemm_f16_splitk_kernel, cudaFuncAttributeMaxDynamicSharedMemorySize, GEMM_SMEM);
    cudaFuncSetAttribute(attn_kernel, cudaFuncAttributeMaxDynamicSharedMemorySize, (int)sizeof(AttnSmem3));

    // launch 0: concat + fp16
    concat_f16_kernel<<<(Bb*LKt*(DM/4)+255)/256, 256>>>(im, docqa, full);
    // launch 1: weight converts
    wconv_w_kernel<<<(SEG_WEND+255)/256, 256>>>(Wq, Wk, Wv, Wo, W1, W2,
                                                wq16, wk16, wv16, wo16, w116, w216);
    // launch 2: bias concat (tiny)
    bias_cat_kernel<<<(KVS+255)/256, 256>>>(bk, bv, p_bkv);
    // launch 3 (profiled): merged Q + KV projections
    qkv_kernel<<<852, 256, GEMM_SMEM>>>(full, wq16, wk16, wv16, bq, p_bkv, q, kv);
    // launch 4: split-K2 attention
    attn_kernel<<<dim3(LQ/64, BHn, 2), 128, sizeof(AttnSmem3)>>>(
        q, kv, dqx, dqy, imx, imy, bias_x, bias_y, p_po, p_pl);
    // launch 5: attention combine
    attn_combine_kernel<<<(BHn*LQ*(DKh/2)+255)/256, 256>>>(p_po, p_pl, ctx);
    // launch 6: output projection (split-K2)
    gemm_f16_splitk_kernel<<<dim3(DM/128, MQn/128, 2), 256, GEMM_SMEM>>>(
        ctx, DM, wo16, DM, bo, p_zeros, p_tmp, p_tmp2, MQn, DM, DM/2);
    // launch 7: add + LN1 (sums both partials)
    addln_kernel<true,true><<<MQn, 256>>>(docqa, p_tmp, p_tmp2, g1, be1, p_src1, s1);
    // launch 8: FFN up + ReLU
    gemm_f16_kernel<1,true><<<dim3(DFFn/128, MQn/128), 256, GEMM_SMEM>>>(
        s1, w116, DFFn, b1, nullptr, f1, MQn, DFFn, DM);
    // launch 9: FFN down (split-K2)
    gemm_f16_splitk_kernel<<<dim3(DM/128, MQn/128, 2), 256, GEMM_SMEM>>>(
        f1, DFFn, w216, DM, b2, p_zeros, p_tmp, p_tmp2, MQn, DM, DFFn/2);
    // launch 10: add + LN2 -> out
    addln_kernel<false,true><<<MQn, 256>>>(p_src1, p_tmp, p_tmp2, g2, be2, out, nullptr);
}

// round 16
// speedup vs baseline: 1.5147x; 1.5147x over previous
#include <cuda_runtime.h>
#include <cuda_fp16.h>
#include <math.h>
#include <stdint.h>

#define Bb 4
#define LQ 640
#define LIMt 1296
#define LKt 1936
#define DM 768
#define NH 12
#define DKh 64
#define DFFn 3072
#define MD 100
#define KVS 1536
#define MQn (Bb*LQ)    // 2560
#define MKn (Bb*LKt)   // 7744
#define BHn (Bb*NH)    // 48

// ================= helpers =================
__device__ __forceinline__ uint32_t smem_to_u32(const void* p) {
    uint32_t a;
    asm("{ .reg .u64 t; cvta.to.shared.u64 t, %1; cvt.u32.u64 %0, t; }" : "=r"(a) : "l"(p));
    return a;
}
__device__ __forceinline__ void cp_async16(uint32_t dst, const void* src, int src_bytes) {
    asm volatile("cp.async.cg.shared.global [%0], [%1], 16, %2;"
                 :: "r"(dst), "l"(src), "r"(src_bytes) : "memory");
}
__device__ __forceinline__ void cp_async4(uint32_t dst, const void* src, int src_bytes) {
    asm volatile("cp.async.ca.shared.global [%0], [%1], 4, %2;"
                 :: "r"(dst), "l"(src), "r"(src_bytes) : "memory");
}
__device__ __forceinline__ void cp_commit() {
    asm volatile("cp.async.commit_group;" ::: "memory");
}
template<int N>
__device__ __forceinline__ void cp_wait() {
    asm volatile("cp.async.wait_group %0;" :: "n"(N) : "memory");
}
__device__ __forceinline__ void ldm_x4(uint32_t& r0, uint32_t& r1, uint32_t& r2, uint32_t& r3,
                                       uint32_t addr) {
    asm volatile("ldmatrix.sync.aligned.m8n8.x4.shared.b16 {%0,%1,%2,%3}, [%4];"
                 : "=r"(r0), "=r"(r1), "=r"(r2), "=r"(r3) : "r"(addr));
}
__device__ __forceinline__ void ldm_x4t(uint32_t& r0, uint32_t& r1, uint32_t& r2, uint32_t& r3,
                                        uint32_t addr) {
    asm volatile("ldmatrix.sync.aligned.m8n8.x4.trans.shared.b16 {%0,%1,%2,%3}, [%4];"
                 : "=r"(r0), "=r"(r1), "=r"(r2), "=r"(r3) : "r"(addr));
}
__device__ __forceinline__ void mma16816(float& d0, float& d1, float& d2, float& d3,
                                         uint32_t a0, uint32_t a1, uint32_t a2, uint32_t a3,
                                         uint32_t b0, uint32_t b1) {
    asm volatile("mma.sync.aligned.m16n8k16.row.col.f32.f16.f16.f32 "
                 "{%0,%1,%2,%3}, {%4,%5,%6,%7}, {%8,%9}, {%0,%1,%2,%3};"
                 : "+f"(d0), "+f"(d1), "+f"(d2), "+f"(d3)
                 : "r"(a0), "r"(a1), "r"(a2), "r"(a3), "r"(b0), "r"(b1));
}

// ================= scratch =================
__device__ float g_tmp [Bb*LQ*DM];
__device__ float g_tmp2[Bb*LQ*DM];
__device__ float g_src1[Bb*LQ*DM];
__device__ float g_bkv [KVS];
__device__ float g_zeros[DFFn];
__device__ float g_po[2*BHn*LQ*DKh];
__device__ float g_pl[2*BHn*LQ];

__device__ __half g_full[Bb*LKt*DM];
__device__ __half g_q   [Bb*LQ*DM];
__device__ __half g_kv  [Bb*LKt*KVS];
__device__ __half g_ctx [Bb*LQ*DM];
__device__ __half g_s1  [Bb*LQ*DM];
__device__ __half g_f1  [Bb*LQ*DFFn];
__device__ __half g_wq16[DM*DM];
__device__ __half g_wk16[DM*DM];
__device__ __half g_wv16[DM*DM];
__device__ __half g_wo16[DM*DM];
__device__ __half g_w116[DM*DFFn];
__device__ __half g_w216[DFFn*DM];

// ================= converts =================
__global__ void concat_f16_kernel(const float* __restrict__ im, const float* __restrict__ doc,
                                  __half* __restrict__ O) {
    int i = blockIdx.x * blockDim.x + threadIdx.x;
    const int total4 = Bb*LKt*(DM/4);
    if (i >= total4) return;
    int d4 = i % (DM/4); int bt = i / (DM/4);
    int b = bt / LKt, t = bt % LKt;
    const float* src = (t < LIMt) ? im + ((size_t)b*LIMt + t)*DM
                                  : doc + ((size_t)b*LQ + (t - LIMt))*DM;
    float4 v = *(const float4*)(src + d4*4);
    __half2* o = (__half2*)(O + (size_t)i*4);
    o[0] = __floats2half2_rn(v.x, v.y);
    o[1] = __floats2half2_rn(v.z, v.w);
}

#define SWF4   147456
#define W1F4   589824
#define SEG_W1 (4*SWF4)
#define SEG_W2 (SEG_W1 + W1F4)
#define SEG_WEND (SEG_W2 + W1F4)

__global__ void wconv_w_kernel(
    const float* __restrict__ Wq, const float* __restrict__ Wk,
    const float* __restrict__ Wv, const float* __restrict__ Wo,
    const float* __restrict__ W1, const float* __restrict__ W2,
    __half* __restrict__ q16, __half* __restrict__ k16,
    __half* __restrict__ v16, __half* __restrict__ o16,
    __half* __restrict__ w116, __half* __restrict__ w216)
{
    int i = blockIdx.x * blockDim.x + threadIdx.x;
    if (i >= SEG_WEND) return;
    const float* src; __half* dst; int j;
    if (i < SEG_W1) {
        int seg = i / SWF4; j = i - seg*SWF4;
        src = seg==0 ? Wq : seg==1 ? Wk : seg==2 ? Wv : Wo;
        dst = seg==0 ? q16 : seg==1 ? k16 : seg==2 ? v16 : o16;
    } else if (i < SEG_W2) { j = i - SEG_W1; src = W1; dst = w116; }
    else                   { j = i - SEG_W2; src = W2; dst = w216; }
    float4 v = ((const float4*)src)[j];
    __half2* o = (__half2*)(dst + (size_t)j*4);
    o[0] = __floats2half2_rn(v.x, v.y);
    o[1] = __floats2half2_rn(v.z, v.w);
}

__global__ void bias_cat_kernel(const float* __restrict__ bk, const float* __restrict__ bv,
                                float* __restrict__ bkv) {
    int i = blockIdx.x * blockDim.x + threadIdx.x;
    if (i < DM) bkv[i] = bk[i];
    else if (i < KVS) bkv[i] = bv[i - DM];
}

// ================= fp16 HMMA GEMM body (single barrier per stage) =================
#define KT 64
#define AROWB 144
#define ATILEB (128*AROWB)
#define BROWB 272
#define BTILEB (64*BROWB)
#define STAGEB (ATILEB+BTILEB)
#define GEMM_SMEM (3*STAGEB)  // 107520

template<int OUTM, bool RELU>
__device__ __forceinline__ void gemm_body(
    const __half* __restrict__ A, int lda, int arow0, bool guard, int M, int m0,
    const __half* __restrict__ Bp, int ldb, int nc0,
    const float* __restrict__ bias, int n0,
    float* __restrict__ C, __half* __restrict__ O16, int ldo,
    int K, uint32_t sbase)
{
    const int tid = threadIdx.x, wid = tid >> 5, lane = tid & 31;
    const int wm = wid & 1, wn = wid >> 1;
    const int KC = K / KT;

    float acc[4][4][4];
    #pragma unroll
    for (int i=0;i<4;i++)
        #pragma unroll
        for (int j=0;j<4;j++)
            #pragma unroll
            for (int r=0;r<4;r++) acc[i][j][r] = 0.f;

    const int lr = tid >> 3;
    const int lc = tid & 7;

    auto issue_chunk = [&](int c) {
        const int buf = c % 3;
        const int k0 = c * KT;
        uint32_t sA = sbase + buf * STAGEB;
        uint32_t sB = sA + ATILEB;
        #pragma unroll
        for (int it = 0; it < 4; it++) {
            int r = lr + it * 32;
            int nb = (!guard || (m0 + r) < M) ? 16 : 0;
            cp_async16(sA + r*AROWB + lc*16,
                       A + (size_t)(arow0 + r) * lda + k0 + lc*8, nb);
        }
        #pragma unroll
        for (int it = 0; it < 4; it++) {
            int e = tid + it * 256;
            int rb = e >> 4, cb = e & 15;
            cp_async16(sB + rb*BROWB + cb*16,
                       Bp + (size_t)(k0 + rb) * ldb + nc0 + cb*8, 16);
        }
        cp_commit();
    };

    issue_chunk(0);
    issue_chunk(1);
    for (int c = 0; c < KC; c++) {
        if (c + 1 < KC) { cp_wait<1>(); }
        else            { cp_wait<0>(); }
        __syncthreads();                 // all warps done with compute(c-1) AND chunk c visible
        if (c + 2 < KC) issue_chunk(c + 2);   // safe: buf (c+2)%3 consumed at iter c-1

        const int buf = c % 3;
        uint32_t sA = sbase + buf * STAGEB;
        uint32_t sB = sA + ATILEB;
        uint32_t aRowBase = sA + (wm*64 + (lane & 15)) * AROWB + (lane >> 4) * 16;
        uint32_t bTBase   = sB + (((lane >> 3) & 1)*8 + (lane & 7)) * BROWB
                               + (lane >> 4) * 16 + wn*64;

        #pragma unroll
        for (int ks = 0; ks < 4; ks++) {
            uint32_t bfr[4][2];
            #pragma unroll
            for (int g = 0; g < 2; g++) {
                uint32_t r0, r1, r2, r3;
                ldm_x4t(r0, r1, r2, r3, bTBase + ks*16*BROWB + g*32);
                bfr[g*2+0][0] = r0; bfr[g*2+0][1] = r1;
                bfr[g*2+1][0] = r2; bfr[g*2+1][1] = r3;
            }
            #pragma unroll
            for (int mt = 0; mt < 4; mt++) {
                uint32_t a0, a1, a2, a3;
                ldm_x4(a0, a1, a2, a3, aRowBase + mt*16*AROWB + ks*32);
                #pragma unroll
                for (int nt = 0; nt < 4; nt++)
                    mma16816(acc[mt][nt][0], acc[mt][nt][1], acc[mt][nt][2], acc[mt][nt][3],
                             a0, a1, a2, a3, bfr[nt][0], bfr[nt][1]);
            }
        }
    }

    const int mr = lane >> 2, nc = (lane & 3) * 2;
    #pragma unroll
    for (int mt = 0; mt < 4; mt++) {
        #pragma unroll
        for (int half = 0; half < 2; half++) {
            int m = m0 + wm*64 + mt*16 + mr + half*8;
            if (guard && m >= M) continue;
            #pragma unroll
            for (int nt = 0; nt < 4; nt++) {
                int n = n0 + wn*32 + nt*8 + nc;
                float v0 = acc[mt][nt][half*2+0] + bias[n];
                float v1 = acc[mt][nt][half*2+1] + bias[n+1];
                if (RELU) { v0 = fmaxf(v0, 0.f); v1 = fmaxf(v1, 0.f); }
                size_t o = (size_t)m * ldo + n;
                if (OUTM == 1) {
                    *reinterpret_cast<__half2*>(O16 + o) = __floats2half2_rn(v0, v1);
                } else {
                    C[o] = v0; C[o+1] = v1;
                }
            }
        }
    }
}

template<int OUTM, bool RELU>
__global__ void __launch_bounds__(256,2) gemm_f16_kernel(
    const __half* __restrict__ A, const __half* __restrict__ Bp, int ldb,
    const float* __restrict__ bias,
    float* __restrict__ C, __half* __restrict__ O16,
    int M, int N, int K)
{
    extern __shared__ char smem[];
    int m0 = blockIdx.y * 128, n0 = blockIdx.x * 128;
    gemm_body<OUTM,RELU>(A, K, m0, true, M, m0, Bp, ldb, n0, bias, n0,
                         C, O16, N, K, smem_to_u32(smem));
}

__global__ void __launch_bounds__(256,2) gemm_f16_splitk_kernel(
    const __half* __restrict__ A, int lda,
    const __half* __restrict__ Bp, int ldb,
    const float* __restrict__ bias, const float* __restrict__ zbias,
    float* __restrict__ C0, float* __restrict__ C1,
    int M, int N, int Ksl)
{
    extern __shared__ char smem[];
    int m0 = blockIdx.y * 128, n0 = blockIdx.x * 128;
    int z = blockIdx.z;
    int kofs = z * Ksl;
    gemm_body<0,false>(A + kofs, lda, m0, true, M, m0,
                       Bp + (size_t)kofs*ldb, ldb, n0,
                       z ? zbias : bias, n0,
                       z ? C1 : C0, nullptr, N, Ksl, smem_to_u32(smem));
}

__global__ void __launch_bounds__(256,2) qkv_kernel(
    const __half* __restrict__ full,
    const __half* __restrict__ wq, const __half* __restrict__ wk, const __half* __restrict__ wv,
    const float* __restrict__ bq, const float* __restrict__ bkv,
    __half* __restrict__ q, __half* __restrict__ kv)
{
    extern __shared__ char smem[];
    uint32_t sbase = smem_to_u32(smem);
    int id = blockIdx.x;
    if (id < 732) {
        int bx = id % 12, by = id / 12;
        int m0 = by*128, n0 = bx*128;
        const __half* Bp = (n0 < DM) ? wk : wv;
        int nc0 = (n0 < DM) ? n0 : n0 - DM;
        gemm_body<1,false>(full, DM, m0, true, MKn, m0, Bp, DM, nc0, bkv, n0,
                           nullptr, kv, KVS, DM, sbase);
    } else {
        int id2 = id - 732;
        int bx = id2 % 6, by = id2 / 6;
        int m0 = by*128, n0 = bx*128;
        int arow0 = (by/5)*LKt + LIMt + (by%5)*128;
        gemm_body<1,false>(full, DM, arow0, false, MQn, m0, wq, DM, n0, bq, n0,
                           nullptr, q, DM, DM, sbase);
    }
}

// ================= fp16 HMMA flash attention (round-14 body, verbatim) =================
#define ATS 72
#define ATSB 144

struct AttnSmem3 {
    __half Q[64*ATS];
    __half K[2][64*ATS], V[2][64*ATS];
    float bx[201], by[201];
    int qx[64], qy[64];
    int2 kxy[2][64];
};

#define CSC 0.18033688011116f   /* 0.125 * log2(e) */
#define M0H 3.0f

__global__ void __launch_bounds__(128,4) attn_kernel(
    const __half* __restrict__ qg, const __half* __restrict__ kvg,
    const int* __restrict__ dqx, const int* __restrict__ dqy,
    const int* __restrict__ imx, const int* __restrict__ imy,
    const float* __restrict__ bias_x, const float* __restrict__ bias_y,
    float* __restrict__ po, float* __restrict__ pl)
{
    extern __shared__ char smem_raw[];
    AttnSmem3& S = *reinterpret_cast<AttnSmem3*>(smem_raw);
    const int tid = threadIdx.x;
    const int lane = tid & 31, w = tid >> 5;
    const int qt = blockIdx.x;
    const int bh = blockIdx.y;
    const int z  = blockIdx.z;
    const int b = bh / NH, h = bh % NH;
    const int qbase = qt * 64;
    const int bLK = b * LKt;
    const int hd = h * DKh;

    const int NT = (LKt + 63) / 64;      // 31
    const int kt0 = z * 16;
    const int kt1 = z ? NT : 16;

    const uint32_t sQ = smem_to_u32(S.Q);
    uint32_t sK[2] = { smem_to_u32(S.K[0]), smem_to_u32(S.K[1]) };
    uint32_t sV[2] = { smem_to_u32(S.V[0]), smem_to_u32(S.V[1]) };
    uint32_t sKxy[2] = { smem_to_u32(S.kxy[0]), smem_to_u32(S.kxy[1]) };

    #pragma unroll
    for (int it = 0; it < 4; it++) {
        int ch = tid + it*128;
        int row = ch >> 3, off = (ch & 7) * 8;
        size_t g = (size_t)(b*LQ + qbase + row)*DM + hd + off;
        *(float4*)((char*)S.Q + row*ATSB + off*2) = *(const float4*)(qg + g);
    }
    const float LOG2E = 1.4426950408889634f;
    for (int i = tid; i < 201; i += 128) {
        S.bx[i] = fmaf(bias_x[i*NH + h], LOG2E, -M0H);
        S.by[i] = fmaf(bias_y[i*NH + h], LOG2E, -M0H);
    }
    if (tid < 64) S.qx[tid] = dqx[b*LQ + qbase + tid];
    else if (tid < 128) S.qy[tid-64] = dqy[b*LQ + qbase + (tid-64)];

    auto issue_kv = [&](int kt) {
        const int buf = kt & 1;
        const int kbase = kt * 64;
        #pragma unroll
        for (int it = 0; it < 4; it++) {
            int ch = tid + it*128;
            int row = ch >> 3, off = (ch & 7) * 8;
            int kg = kbase + row;
            int nb = kg < LKt ? 16 : 0;
            size_t g = (size_t)(bLK + kg)*KVS + hd + off;
            uint32_t so = row*ATSB + off*2;
            cp_async16(sK[buf] + so, kvg + g, nb);
            cp_async16(sV[buf] + so, kvg + g + DM, nb);
        }
        {
            int j = tid & 63;
            int kg = kbase + j;
            const int* src;
            if (tid < 64) src = (kg < LIMt) ? (imx + b*LIMt + kg) : (dqx + b*LQ + (kg - LIMt));
            else          src = (kg < LIMt) ? (imy + b*LIMt + kg) : (dqy + b*LQ + (kg - LIMt));
            uint32_t dst = sKxy[buf] + j*8 + (tid < 64 ? 0 : 4);
            cp_async4(dst, src, kg < LKt ? 4 : 0);
        }
        cp_commit();
    };

    issue_kv(kt0);
    __syncthreads();

    const int r1 = w*16 + (lane >> 2);
    const int qx1 = S.qx[r1],   qy1 = S.qy[r1];
    const int qx2 = S.qx[r1+8], qy2 = S.qy[r1+8];

    uint32_t qa[4][4];
    {
        uint32_t aBase = (w*16 + (lane & 15))*ATSB + (lane >> 4)*16;
        #pragma unroll
        for (int s = 0; s < 4; s++)
            ldm_x4(qa[s][0], qa[s][1], qa[s][2], qa[s][3], sQ + aBase + s*32);
    }

    float oacc[8][4];
    #pragma unroll
    for (int d=0; d<8; d++)
        #pragma unroll
        for (int r=0; r<4; r++) oacc[d][r] = 0.f;
    float l1 = 0.f, l2 = 0.f;

    for (int kt = kt0; kt < kt1; kt++) {
        if (kt > kt0) __syncthreads();
        if (kt + 1 < kt1) { issue_kv(kt + 1); cp_wait<1>(); }
        else              { cp_wait<0>(); }
        __syncthreads();

        const int buf = kt & 1;
        const int kbase = kt * 64;

        float sc[8][4];
        #pragma unroll
        for (int nt=0; nt<8; nt++)
            #pragma unroll
            for (int r=0; r<4; r++) sc[nt][r] = 0.f;

        uint32_t bBase = (lane & 15)*ATSB + (lane >> 4)*16;
        #pragma unroll
        for (int s = 0; s < 4; s++) {
            uint32_t bf[8][2];
            #pragma unroll
            for (int np = 0; np < 4; np++) {
                uint32_t r0, r1_, r2_, r3_;
                ldm_x4(r0, r1_, r2_, r3_, sK[buf] + bBase + np*16*ATSB + s*32);
                bf[np*2+0][0] = r0;  bf[np*2+0][1] = r2_;
                bf[np*2+1][0] = r1_; bf[np*2+1][1] = r3_;
            }
            #pragma unroll
            for (int nt = 0; nt < 8; nt++)
                mma16816(sc[nt][0], sc[nt][1], sc[nt][2], sc[nt][3],
                         qa[s][0], qa[s][1], qa[s][2], qa[s][3], bf[nt][0], bf[nt][1]);
        }

        // ---- bias + exp (fixed max; MUFU EX2; int2 coord load; SEL mask) ----
        #pragma unroll
        for (int nt = 0; nt < 8; nt++) {
            #pragma unroll
            for (int e = 0; e < 2; e++) {
                int c = nt*8 + (lane & 3)*2 + e;
                int2 kk = S.kxy[buf][c];
                bool valid = (kbase + c) < LKt;
                int rx1 = qx1 - kk.x; rx1 = rx1 < -MD ? -MD : (rx1 > MD ? MD : rx1);
                int ry1 = qy1 - kk.y; ry1 = ry1 < -MD ? -MD : (ry1 > MD ? MD : ry1);
                float b1v = S.bx[rx1 + MD] + S.by[ry1 + MD];
                float p0 = exp2f(fmaf(sc[nt][e], CSC, b1v));
                int rx2 = qx2 - kk.x; rx2 = rx2 < -MD ? -MD : (rx2 > MD ? MD : rx2);
                int ry2 = qy2 - kk.y; ry2 = ry2 < -MD ? -MD : (ry2 > MD ? MD : ry2);
                float b2v = S.bx[rx2 + MD] + S.by[ry2 + MD];
                float p1 = exp2f(fmaf(sc[nt][2+e], CSC, b2v));
                p0 = valid ? p0 : 0.f;
                p1 = valid ? p1 : 0.f;
                sc[nt][e] = p0;   l1 += p0;
                sc[nt][2+e] = p1; l2 += p1;
            }
        }

        // ---- O += P V (pack pa inside the loop) ----
        uint32_t vBase = (((lane >> 3) & 1)*8 + (lane & 7))*ATSB + (lane >> 4)*16;
        #pragma unroll
        for (int t = 0; t < 4; t++) {
            uint32_t pa0, pa1, pa2, pa3;
            {
                __half2 h0 = __floats2half2_rn(sc[2*t][0],   sc[2*t][1]);
                __half2 h1 = __floats2half2_rn(sc[2*t][2],   sc[2*t][3]);
                __half2 h2 = __floats2half2_rn(sc[2*t+1][0], sc[2*t+1][1]);
                __half2 h3 = __floats2half2_rn(sc[2*t+1][2], sc[2*t+1][3]);
                pa0 = *reinterpret_cast<uint32_t*>(&h0);
                pa1 = *reinterpret_cast<uint32_t*>(&h1);
                pa2 = *reinterpret_cast<uint32_t*>(&h2);
                pa3 = *reinterpret_cast<uint32_t*>(&h3);
            }
            #pragma unroll
            for (int dp = 0; dp < 4; dp++) {
                uint32_t v0, v1, v2, v3;
                ldm_x4t(v0, v1, v2, v3, sV[buf] + vBase + t*16*ATSB + dp*32);
                mma16816(oacc[dp*2][0], oacc[dp*2][1], oacc[dp*2][2], oacc[dp*2][3],
                         pa0, pa1, pa2, pa3, v0, v1);
                mma16816(oacc[dp*2+1][0], oacc[dp*2+1][1], oacc[dp*2+1][2], oacc[dp*2+1][3],
                         pa0, pa1, pa2, pa3, v2, v3);
            }
        }
    }

    // ---- partial row sums + partial O to scratch ----
    l1 += __shfl_xor_sync(0xffffffffu, l1, 1);
    l1 += __shfl_xor_sync(0xffffffffu, l1, 2);
    l2 += __shfl_xor_sync(0xffffffffu, l2, 1);
    l2 += __shfl_xor_sync(0xffffffffu, l2, 2);
    const int qrow1 = qbase + r1, qrow2 = qrow1 + 8;
    const size_t zofs = (size_t)z * BHn * LQ;
    if ((lane & 3) == 0) {
        pl[zofs + (size_t)bh*LQ + qrow1] = l1;
        pl[zofs + (size_t)bh*LQ + qrow2] = l2;
    }
    const size_t pbase1 = (zofs + (size_t)bh*LQ + qrow1) * DKh;
    const size_t pbase2 = (zofs + (size_t)bh*LQ + qrow2) * DKh;
    #pragma unroll
    for (int d = 0; d < 8; d++) {
        int colp = d*8 + (lane & 3)*2;
        *(float2*)(po + pbase1 + colp) = make_float2(oacc[d][0], oacc[d][1]);
        *(float2*)(po + pbase2 + colp) = make_float2(oacc[d][2], oacc[d][3]);
    }
}

// combine: ctx = (O0+O1)/(l0+l1), fp16
__global__ void __launch_bounds__(256) attn_combine_kernel(
    const float* __restrict__ po, const float* __restrict__ pl,
    __half* __restrict__ ctx)
{
    int t = blockIdx.x * blockDim.x + threadIdx.x;
    const int total = BHn*LQ*(DKh/2);
    if (t >= total) return;
    int d2 = (t & 31) * 2;
    int bhq = t >> 5;
    const size_t Z = (size_t)BHn*LQ;
    float l = pl[bhq] + pl[Z + bhq];
    float inv = 1.f / l;
    float2 o0 = *(const float2*)(po + (size_t)bhq*DKh + d2);
    float2 o1 = *(const float2*)(po + (Z + bhq)*DKh + d2);
    int bh = bhq / LQ, qr = bhq % LQ;
    int b = bh / NH, h = bh % NH;
    size_t o = ((size_t)(b*LQ + qr))*DM + h*DKh + d2;
    *reinterpret_cast<__half2*>(ctx + o) =
        __floats2half2_rn((o0.x + o1.x)*inv, (o0.y + o1.y)*inv);
}

// ================= fused add + LayerNorm =================
template<bool F16OUT, bool TWO>
__global__ void __launch_bounds__(256) addln_kernel(
    const float* __restrict__ A, const float* __restrict__ Cv, const float* __restrict__ Cv2,
    const float* __restrict__ g, const float* __restrict__ be,
    float* __restrict__ out, __half* __restrict__ O16)
{
    __shared__ float sred[256];
    const int row = blockIdx.x;
    const int tid = threadIdx.x;
    const size_t base = (size_t)row * DM;

    float x[3];
    #pragma unroll
    for (int i=0;i<3;i++) {
        int col = tid + 256*i;
        x[i] = A[base + col] + Cv[base + col];
        if (TWO) x[i] += Cv2[base + col];
    }
    float s = x[0] + x[1] + x[2];
    sred[tid] = s; __syncthreads();
    for (int off=128; off>0; off>>=1) {
        if (tid < off) sred[tid] += sred[tid+off];
        __syncthreads();
    }
    float mu = sred[0] * (1.f/DM);
    __syncthreads();
    float d0=x[0]-mu, d1=x[1]-mu, d2=x[2]-mu;
    sred[tid] = d0*d0 + d1*d1 + d2*d2; __syncthreads();
    for (int off=128; off>0; off>>=1) {
        if (tid < off) sred[tid] += sred[tid+off];
        __syncthreads();
    }
    float rs = rsqrtf(sred[0] * (1.f/DM) + 1e-5f);
    #pragma unroll
    for (int i=0;i<3;i++) {
        int col = tid + 256*i;
        float v = (x[i] - mu) * rs * g[col] + be[col];
        out[base + col] = v;
        if (F16OUT) O16[base + col] = __float2half_rn(v);
    }
}

// ================= launch =================
extern "C" void kernel_launch(void* const* d_in, const int* in_sizes, int n_in,
                              void* d_out, int out_size) {
    const float* docqa  = (const float*)d_in[0];
    const float* im     = (const float*)d_in[1];
    const int*   dqx    = (const int*)  d_in[2];
    const int*   dqy    = (const int*)  d_in[3];
    const int*   imx    = (const int*)  d_in[4];
    const int*   imy    = (const int*)  d_in[5];
    const float* Wq     = (const float*)d_in[6];
    const float* bq     = (const float*)d_in[7];
    const float* Wk     = (const float*)d_in[8];
    const float* bk     = (const float*)d_in[9];
    const float* Wv     = (const float*)d_in[10];
    const float* bv     = (const float*)d_in[11];
    const float* Wo     = (const float*)d_in[12];
    const float* bo     = (const float*)d_in[13];
    const float* bias_x = (const float*)d_in[14];
    const float* bias_y = (const float*)d_in[15];
    const float* W1     = (const float*)d_in[16];
    const float* b1     = (const float*)d_in[17];
    const float* W2     = (const float*)d_in[18];
    const float* b2     = (const float*)d_in[19];
    const float* g1     = (const float*)d_in[20];
    const float* be1    = (const float*)d_in[21];
    const float* g2     = (const float*)d_in[22];
    const float* be2    = (const float*)d_in[23];
    float* out = (float*)d_out;

    float *p_tmp, *p_tmp2, *p_src1, *p_bkv, *p_zeros, *p_po, *p_pl;
    cudaGetSymbolAddress((void**)&p_tmp,  g_tmp);
    cudaGetSymbolAddress((void**)&p_tmp2, g_tmp2);
    cudaGetSymbolAddress((void**)&p_src1, g_src1);
    cudaGetSymbolAddress((void**)&p_bkv,  g_bkv);
    cudaGetSymbolAddress((void**)&p_zeros,g_zeros);
    cudaGetSymbolAddress((void**)&p_po,   g_po);
    cudaGetSymbolAddress((void**)&p_pl,   g_pl);

    __half *full, *q, *kv, *ctx, *s1, *f1;
    __half *wq16, *wk16, *wv16, *wo16, *w116, *w216;
    cudaGetSymbolAddress((void**)&full, g_full);
    cudaGetSymbolAddress((void**)&q,    g_q);
    cudaGetSymbolAddress((void**)&kv,   g_kv);
    cudaGetSymbolAddress((void**)&ctx,  g_ctx);
    cudaGetSymbolAddress((void**)&s1,   g_s1);
    cudaGetSymbolAddress((void**)&f1,   g_f1);
    cudaGetSymbolAddress((void**)&wq16, g_wq16);
    cudaGetSymbolAddress((void**)&wk16, g_wk16);
    cudaGetSymbolAddress((void**)&wv16, g_wv16);
    cudaGetSymbolAddress((void**)&wo16, g_wo16);
    cudaGetSymbolAddress((void**)&w116, g_w116);
    cudaGetSymbolAddress((void**)&w216, g_w216);

    cudaFuncSetAttribute(qkv_kernel, cudaFuncAttributeMaxDynamicSharedMemorySize, GEMM_SMEM);
    cudaFuncSetAttribute(gemm_f16_kernel<0,false>, cudaFuncAttributeMaxDynamicSharedMemorySize, GEMM_SMEM);
    cudaFuncSetAttribute(gemm_f16_kernel<1,true >, cudaFuncAttributeMaxDynamicSharedMemorySize, GEMM_SMEM);
    cudaFuncSetAttribute(gemm_f16_splitk_kernel, cudaFuncAttributeMaxDynamicSharedMemorySize, GEMM_SMEM);
    cudaFuncSetAttribute(attn_kernel, cudaFuncAttributeMaxDynamicSharedMemorySize, (int)sizeof(AttnSmem3));

    // launch 0: concat + fp16
    concat_f16_kernel<<<(Bb*LKt*(DM/4)+255)/256, 256>>>(im, docqa, full);
    // launch 1: weight converts
    wconv_w_kernel<<<(SEG_WEND+255)/256, 256>>>(Wq, Wk, Wv, Wo, W1, W2,
                                                wq16, wk16, wv16, wo16, w116, w216);
    // launch 2: bias concat (tiny)
    bias_cat_kernel<<<(KVS+255)/256, 256>>>(bk, bv, p_bkv);
    // launch 3 (profiled): merged Q + KV projections
    qkv_kernel<<<852, 256, GEMM_SMEM>>>(full, wq16, wk16, wv16, bq, p_bkv, q, kv);
    // launch 4: split-K2 attention (round-14 body)
    attn_kernel<<<dim3(LQ/64, BHn, 2), 128, sizeof(AttnSmem3)>>>(
        q, kv, dqx, dqy, imx, imy, bias_x, bias_y, p_po, p_pl);
    // launch 5: attention combine
    attn_combine_kernel<<<(BHn*LQ*(DKh/2)+255)/256, 256>>>(p_po, p_pl, ctx);
    // launch 6: output projection (split-K2)
    gemm_f16_splitk_kernel<<<dim3(DM/128, MQn/128, 2), 256, GEMM_SMEM>>>(
        ctx, DM, wo16, DM, bo, p_zeros, p_tmp, p_tmp2, MQn, DM, DM/2);
    // launch 7: add + LN1 (sums both partials)
    addln_kernel<true,true><<<MQn, 256>>>(docqa, p_tmp, p_tmp2, g1, be1, p_src1, s1);
    // launch 8: FFN up + ReLU
    gemm_f16_kernel<1,true><<<dim3(DFFn/128, MQn/128), 256, GEMM_SMEM>>>(
        s1, w116, DFFn, b1, nullptr, f1, MQn, DFFn, DM);
    // launch 9: FFN down (split-K2)
    gemm_f16_splitk_kernel<<<dim3(DM/128, MQn/128, 2), 256, GEMM_SMEM>>>(
        f1, DFFn, w216, DM, b2, p_zeros, p_tmp, p_tmp2, MQn, DM, DFFn/2);
    // launch 10: add + LN2 -> out
    addln_kernel<false,true><<<MQn, 256>>>(p_src1, p_tmp, p_tmp2, g2, be2, out, nullptr);
}